// round 1
// baseline (speedup 1.0000x reference)
#include <cuda_runtime.h>

// x:        [B,S,C,D] = [32,4096,64,2] float32
// W_nonlin: [C,2,2]   float32  (torch layout [out,in])
// W_coeff:  [C,2,2]   float32
// out:      [B,S,C,2] float32
//
// Per complex pair (x0,x1) with channel c:
//   y0 = x0*Wn[c,0,0] + x1*Wn[c,0,1]
//   y1 = x0*Wn[c,1,0] + x1*Wn[c,1,1]
//   amp = y0*y0 + y1*y1
//   c0 = amp*y0 ; c1 = amp*y1
//   z0 = c0*Wc[c,0,0] + c1*Wc[c,0,1]
//   z1 = c0*Wc[c,1,0] + c1*Wc[c,1,1]

static constexpr int C = 64;
static constexpr int THREADS = 256;

__global__ void __launch_bounds__(THREADS)
cplx_nonlin_kernel(const float4* __restrict__ x4,
                   const float4* __restrict__ wn4,   // [C] float4 = {W[c,0,0],W[c,0,1],W[c,1,0],W[c,1,1]}
                   const float4* __restrict__ wc4,
                   float4* __restrict__ out4,
                   int n4)
{
    __shared__ float4 sWn[C];
    __shared__ float4 sWc[C];

    int t = threadIdx.x;
    if (t < C) {
        sWn[t] = wn4[t];
    } else if (t < 2 * C) {
        sWc[t - C] = wc4[t - C];
    }
    __syncthreads();

    int i = blockIdx.x * THREADS + t;
    if (i >= n4) return;

    float4 v = x4[i];

    // Each float4 covers complex pairs at linear pair-indices 2i and 2i+1.
    // Pairs per (b,s) row = C = 64, so channel = pair_idx & 63.
    int c0 = (2 * i) & (C - 1);   // even channel
    int c1 = c0 + 1;

    float4 a = sWn[c0];
    float4 b = sWn[c1];
    float4 ka = sWc[c0];
    float4 kb = sWc[c1];

    float4 r;

    // pair 0: (v.x, v.y), channel c0
    {
        float y0 = fmaf(v.x, a.x, v.y * a.y);
        float y1 = fmaf(v.x, a.z, v.y * a.w);
        float amp = fmaf(y0, y0, y1 * y1);
        float p0 = amp * y0;
        float p1 = amp * y1;
        r.x = fmaf(p0, ka.x, p1 * ka.y);
        r.y = fmaf(p0, ka.z, p1 * ka.w);
    }

    // pair 1: (v.z, v.w), channel c1
    {
        float y0 = fmaf(v.z, b.x, v.w * b.y);
        float y1 = fmaf(v.z, b.z, v.w * b.w);
        float amp = fmaf(y0, y0, y1 * y1);
        float p0 = amp * y0;
        float p1 = amp * y1;
        r.z = fmaf(p0, kb.x, p1 * kb.y);
        r.w = fmaf(p0, kb.z, p1 * kb.w);
    }

    out4[i] = r;
}

extern "C" void kernel_launch(void* const* d_in, const int* in_sizes, int n_in,
                              void* d_out, int out_size)
{
    const float4* x4  = (const float4*)d_in[0];
    const float4* wn4 = (const float4*)d_in[1];
    const float4* wc4 = (const float4*)d_in[2];
    float4* out4      = (float4*)d_out;

    int n4 = out_size / 4;   // total float4 elements (out_size = B*S*C*2 floats)
    int blocks = (n4 + THREADS - 1) / THREADS;

    cplx_nonlin_kernel<<<blocks, THREADS>>>(x4, wn4, wc4, out4, n4);
}

// round 2
// speedup vs baseline: 1.2500x; 1.2500x over previous
#include <cuda_runtime.h>

// x:        [B,S,C,D] = [32,4096,64,2] float32  -> 131072 rows of 64 complex pairs
// W_nonlin: [C,2,2] float32, W_coeff: [C,2,2] float32
// out:      [B,S,C,2] float32
//
// One row (b,s) = 64 pairs = 32 float4. Lane l of a warp owns float4 column l,
// i.e. channels (2l, 2l+1), for ALL rows it processes. Weights live in registers.

static constexpr int THREADS        = 256;               // 8 warps / block
static constexpr int WARPS_PER_BLK  = THREADS / 32;
static constexpr int ROWS_PER_WARP  = 8;

__global__ void __launch_bounds__(THREADS)
cplx_nonlin_kernel(const float4* __restrict__ x4,
                   const float4* __restrict__ wn4,   // [C] float4 {W[c,0,0],W[c,0,1],W[c,1,0],W[c,1,1]}
                   const float4* __restrict__ wc4,
                   float4* __restrict__ out4,
                   int nrows)                        // B*S
{
    const int lane = threadIdx.x & 31;
    const int warp = (blockIdx.x * WARPS_PER_BLK) + (threadIdx.x >> 5);

    // Per-lane weights: channels 2*lane and 2*lane+1. Loaded once, register-resident.
    const int c0 = 2 * lane;
    const float4 a  = __ldg(&wn4[c0]);
    const float4 b  = __ldg(&wn4[c0 + 1]);
    const float4 ka = __ldg(&wc4[c0]);
    const float4 kb = __ldg(&wc4[c0 + 1]);

    const int row_base = warp * ROWS_PER_WARP;

    #pragma unroll
    for (int k0 = 0; k0 < ROWS_PER_WARP; k0 += 4) {
        float4 v[4];
        int idx[4];
        // Batch 4 independent coalesced loads (MLP=4)
        #pragma unroll
        for (int j = 0; j < 4; j++) {
            int row = row_base + k0 + j;
            idx[j] = row * 32 + lane;
            if (row < nrows) v[j] = x4[idx[j]];
        }
        #pragma unroll
        for (int j = 0; j < 4; j++) {
            int row = row_base + k0 + j;
            if (row >= nrows) continue;
            float4 r;
            // pair 0: (v.x, v.y), channel 2*lane
            {
                float y0  = fmaf(v[j].x, a.x, v[j].y * a.y);
                float y1  = fmaf(v[j].x, a.z, v[j].y * a.w);
                float amp = fmaf(y0, y0, y1 * y1);
                float p0 = amp * y0;
                float p1 = amp * y1;
                r.x = fmaf(p0, ka.x, p1 * ka.y);
                r.y = fmaf(p0, ka.z, p1 * ka.w);
            }
            // pair 1: (v.z, v.w), channel 2*lane+1
            {
                float y0  = fmaf(v[j].z, b.x, v[j].w * b.y);
                float y1  = fmaf(v[j].z, b.z, v[j].w * b.w);
                float amp = fmaf(y0, y0, y1 * y1);
                float p0 = amp * y0;
                float p1 = amp * y1;
                r.z = fmaf(p0, kb.x, p1 * kb.y);
                r.w = fmaf(p0, kb.z, p1 * kb.w);
            }
            out4[idx[j]] = r;
        }
    }
}

extern "C" void kernel_launch(void* const* d_in, const int* in_sizes, int n_in,
                              void* d_out, int out_size)
{
    const float4* x4  = (const float4*)d_in[0];
    const float4* wn4 = (const float4*)d_in[1];
    const float4* wc4 = (const float4*)d_in[2];
    float4* out4      = (float4*)d_out;

    // out_size = B*S*C*2 floats ; one row = C*2 = 128 floats = 32 float4
    int nrows = out_size / 128;                       // 131072
    int warps = (nrows + ROWS_PER_WARP - 1) / ROWS_PER_WARP;
    int blocks = (warps + WARPS_PER_BLK - 1) / WARPS_PER_BLK;   // 2048

    cplx_nonlin_kernel<<<blocks, THREADS>>>(x4, wn4, wc4, out4, nrows);
}

// round 3
// speedup vs baseline: 1.2639x; 1.0111x over previous
#include <cuda_runtime.h>

// x: [32,4096,64,2] f32 = 131072 rows x 64 complex pairs (32 float4 per row)
// Lane l owns float4 column l (channels 2l, 2l+1) for all its rows; weights in regs.

static constexpr int THREADS       = 256;   // 8 warps
static constexpr int WARPS_PER_BLK = THREADS / 32;
static constexpr int ROWS_PER_WARP = 8;
static constexpr int ROW_F4        = 32;    // float4 per row

__device__ __forceinline__ float4 pair2_apply(float4 v, float4 a, float4 b,
                                              float4 ka, float4 kb)
{
    float4 r;
    {   // pair 0: (v.x, v.y)
        float y0  = fmaf(v.x, a.x, v.y * a.y);
        float y1  = fmaf(v.x, a.z, v.y * a.w);
        float amp = fmaf(y0, y0, y1 * y1);
        float p0 = amp * y0, p1 = amp * y1;
        r.x = fmaf(p0, ka.x, p1 * ka.y);
        r.y = fmaf(p0, ka.z, p1 * ka.w);
    }
    {   // pair 1: (v.z, v.w)
        float y0  = fmaf(v.z, b.x, v.w * b.y);
        float y1  = fmaf(v.z, b.z, v.w * b.w);
        float amp = fmaf(y0, y0, y1 * y1);
        float p0 = amp * y0, p1 = amp * y1;
        r.z = fmaf(p0, kb.x, p1 * kb.y);
        r.w = fmaf(p0, kb.z, p1 * kb.w);
    }
    return r;
}

__global__ void __launch_bounds__(THREADS)
cplx_nonlin_kernel(const float4* __restrict__ x4,
                   const float4* __restrict__ wn4,
                   const float4* __restrict__ wc4,
                   float4* __restrict__ out4,
                   int nrows)
{
    const int lane = threadIdx.x & 31;
    const int warp = blockIdx.x * WARPS_PER_BLK + (threadIdx.x >> 5);

    const int c0 = 2 * lane;
    const float4 a  = __ldg(&wn4[c0]);
    const float4 b  = __ldg(&wn4[c0 + 1]);
    const float4 ka = __ldg(&wc4[c0]);
    const float4 kb = __ldg(&wc4[c0 + 1]);

    const int row_base = warp * ROWS_PER_WARP;
    const long base = (long)row_base * ROW_F4 + lane;
    const float4* __restrict__ xp = x4 + base;
    float4* __restrict__ op = out4 + base;

    if (row_base + ROWS_PER_WARP <= nrows) {
        // Hot path: constant immediate offsets, two 4-deep load batches.
        #pragma unroll
        for (int k0 = 0; k0 < ROWS_PER_WARP; k0 += 4) {
            float4 v0 = __ldcs(xp + (k0 + 0) * ROW_F4);
            float4 v1 = __ldcs(xp + (k0 + 1) * ROW_F4);
            float4 v2 = __ldcs(xp + (k0 + 2) * ROW_F4);
            float4 v3 = __ldcs(xp + (k0 + 3) * ROW_F4);
            __stcs(op + (k0 + 0) * ROW_F4, pair2_apply(v0, a, b, ka, kb));
            __stcs(op + (k0 + 1) * ROW_F4, pair2_apply(v1, a, b, ka, kb));
            __stcs(op + (k0 + 2) * ROW_F4, pair2_apply(v2, a, b, ka, kb));
            __stcs(op + (k0 + 3) * ROW_F4, pair2_apply(v3, a, b, ka, kb));
        }
    } else {
        for (int k = 0; k < ROWS_PER_WARP; k++) {
            if (row_base + k >= nrows) break;
            float4 v = __ldcs(xp + k * ROW_F4);
            __stcs(op + k * ROW_F4, pair2_apply(v, a, b, ka, kb));
        }
    }
}

extern "C" void kernel_launch(void* const* d_in, const int* in_sizes, int n_in,
                              void* d_out, int out_size)
{
    const float4* x4  = (const float4*)d_in[0];
    const float4* wn4 = (const float4*)d_in[1];
    const float4* wc4 = (const float4*)d_in[2];
    float4* out4      = (float4*)d_out;

    int nrows  = out_size / 128;                                  // 131072
    int warps  = (nrows + ROWS_PER_WARP - 1) / ROWS_PER_WARP;
    int blocks = (warps + WARPS_PER_BLK - 1) / WARPS_PER_BLK;     // 2048

    cplx_nonlin_kernel<<<blocks, THREADS>>>(x4, wn4, wc4, out4, nrows);
}